// round 3
// baseline (speedup 1.0000x reference)
#include <cuda_runtime.h>
#include <math.h>

// ---------------- problem constants ----------------
#define NB 4096
#define ND 128
#define INV_TEMP 14.285714285714285714f          // 1/0.07
#define KE 20.609929155556619f                   // INV_TEMP * log2(e)
#define LN2 0.69314718055994531f

// ---------------- device scratch (no allocs) ----------------
__device__ float g_Rf[2][NB];
__device__ float g_Rs[2][NB];
__device__ float g_RfM[NB];
__device__ float g_RsM[NB];
__device__ unsigned g_baseBits[32768];           // [256 rows][128 words]
__device__ float g_state[2][NB * 6];             // {Zz, Zm, Sz, Sm, ws, vc} per row per col-split

// ---------------- small helpers ----------------
__device__ __forceinline__ unsigned long long ffma2(unsigned long long a,
                                                    unsigned long long b,
                                                    unsigned long long c) {
    unsigned long long d;
    asm("fma.rn.f32x2 %0, %1, %2, %3;" : "=l"(d) : "l"(a), "l"(b), "l"(c));
    return d;
}
__device__ __forceinline__ float red2(unsigned long long v) {
    float lo = __uint_as_float((unsigned)v);
    float hi = __uint_as_float((unsigned)(v >> 32));
    return lo + hi;
}
__device__ __forceinline__ float ex2f(float x) {
    float r; asm("ex2.approx.ftz.f32 %0, %1;" : "=f"(r) : "f"(x)); return r;
}
__device__ __forceinline__ float lg2f(float x) {
    float r; asm("lg2.approx.ftz.f32 %0, %1;" : "=f"(r) : "f"(x)); return r;
}

// ---------------- smem tile loaders ----------------
// A tile: 64 rows x 128 k, stored as 64 k-pair slices p (pitch 132 floats):
//   [0:64)  : for t=0..15 the 4-float chunk {A[2p][4t],A[2p+1][4t],A[2p][4t+1],A[2p+1][4t+1]}
//   [64:128): same for rows 4t+2, 4t+3
// Read: thread ty does two LDS.128 -> 4 row k-pairs; 16 unique contiguous 16B
// addrs broadcast across tx => conflict-free.
__device__ __forceinline__ void load_A_pairs(float* dst, const float* __restrict__ src,
                                             int g0, int tid) {
    for (int idx = tid; idx < 2048; idx += 256) {
        int row = idx >> 5, dv = idx & 31;
        float4 v = *(const float4*)(src + (size_t)(g0 + row) * ND + (dv << 2));
        int base = ((row & 2) ? 64 : 0) + (row >> 2) * 4 + (row & 1) * 2;
        dst[(2 * dv) * 132 + base + 0]     = v.x;   // k=4dv,   p=2dv
        dst[(2 * dv) * 132 + base + 1]     = v.y;   // k=4dv+1
        dst[(2 * dv + 1) * 132 + base + 0] = v.z;   // k=4dv+2, p=2dv+1
        dst[(2 * dv + 1) * 132 + base + 1] = v.w;   // k=4dv+3
    }
}

// B tile: 64 rows x 128 k row-major, pitch 132 floats (16B-aligned rows).
__device__ __forceinline__ void load_B_pairs(float* dst, const float* __restrict__ src,
                                             int j0, int tid) {
    for (int idx = tid; idx < 2048; idx += 256) {
        int n = idx >> 5, dv = idx & 31;
        *(float4*)(dst + n * 132 + (dv << 2)) =
            *(const float4*)(src + (size_t)(j0 + n) * ND + (dv << 2));
    }
}

// Dual 64x64x128 gemm with packed f32x2 FMAs. acc*[16] are f32x2 accumulators
// (lo/hi = even/odd k split); final value = red2().
__device__ __forceinline__ void gemm2(const float* __restrict__ A0, const float* __restrict__ A1,
                                      const float* __restrict__ B0, const float* __restrict__ B1,
                                      int ty, int tx,
                                      unsigned long long c0[16], unsigned long long c1[16]) {
#pragma unroll
    for (int i = 0; i < 16; i++) { c0[i] = 0ull; c1[i] = 0ull; }
    const float* a0 = A0 + ty * 4;
    const float* a1 = A1 + ty * 4;
    const float* b0 = B0 + tx * 4 * 132;
    const float* b1 = B1 + tx * 4 * 132;
#pragma unroll 4
    for (int p = 0; p < 64; p++) {
        ulonglong2 a0lo = *(const ulonglong2*)(a0 + p * 132);
        ulonglong2 a0hi = *(const ulonglong2*)(a0 + p * 132 + 64);
        ulonglong2 a1lo = *(const ulonglong2*)(a1 + p * 132);
        ulonglong2 a1hi = *(const ulonglong2*)(a1 + p * 132 + 64);
        unsigned long long ar0[4] = {a0lo.x, a0lo.y, a0hi.x, a0hi.y};
        unsigned long long ar1[4] = {a1lo.x, a1lo.y, a1hi.x, a1hi.y};
        unsigned long long b0v[4], b1v[4];
#pragma unroll
        for (int c = 0; c < 4; c++) {
            b0v[c] = *(const unsigned long long*)(b0 + c * 132 + 2 * p);
            b1v[c] = *(const unsigned long long*)(b1 + c * 132 + 2 * p);
        }
#pragma unroll
        for (int r = 0; r < 4; r++)
#pragma unroll
            for (int c = 0; c < 4; c++) {
                c0[r * 4 + c] = ffma2(ar0[r], b0v[c], c0[r * 4 + c]);
                c1[r * 4 + c] = ffma2(ar1[r], b1v[c], c1[r * 4 + c]);
            }
    }
}

// ---------------- kernel 0: pack neglect-base mask to bits ----------------
__global__ void pack_kernel(const float* __restrict__ base) {
    int w = blockIdx.x * 256 + threadIdx.x;     // 32768 words
    const float* p = base + (size_t)w * 32;
    unsigned bits = 0;
#pragma unroll
    for (int b = 0; b < 32; b++) bits |= (p[b] > 0.f) ? (1u << b) : 0u;
    g_baseBits[w] = bits;
}

// ---------------- kernel 1: pool row-maxes ----------------
// grid (64 row-tiles, 2 pool-halves). Rf[i]=max_k<f_i,pag_k>, Rs[i]=max_k<s_i,psp_k>.
__global__ void __launch_bounds__(256, 1)
rmax_kernel(const float* __restrict__ f, const float* __restrict__ spr,
            const float* __restrict__ pag, const float* __restrict__ psp) {
    extern __shared__ float sm[];
    int tid = threadIdx.x, tx = tid >> 4, ty = tid & 15;
    int g0 = blockIdx.x * 64, p0 = blockIdx.y * 512;
    float* A0 = sm;
    float* A1 = sm + 8448;
    float* B0 = sm + 16896;
    float* B1 = sm + 25344;

    load_A_pairs(A0, f, g0, tid);
    load_A_pairs(A1, spr, g0, tid);

    float rmf[4], rms[4];
#pragma unroll
    for (int r = 0; r < 4; r++) { rmf[r] = -1e30f; rms[r] = -1e30f; }

    for (int jt = 0; jt < 8; jt++) {
        __syncthreads();
        load_B_pairs(B0, pag, p0 + jt * 64, tid);
        load_B_pairs(B1, psp, p0 + jt * 64, tid);
        __syncthreads();
        unsigned long long c0[16], c1[16];
        gemm2(A0, A1, B0, B1, ty, tx, c0, c1);
#pragma unroll
        for (int r = 0; r < 4; r++)
#pragma unroll
            for (int c = 0; c < 4; c++) {
                rmf[r] = fmaxf(rmf[r], red2(c0[r * 4 + c]));
                rms[r] = fmaxf(rms[r], red2(c1[r * 4 + c]));
            }
    }
    __syncthreads();
#pragma unroll
    for (int r = 0; r < 4; r++) {
        sm[(4 * ty + r) * 32 + tx] = rmf[r];
        sm[2048 + (4 * ty + r) * 32 + tx] = rms[r];
    }
    __syncthreads();
    if (tid < 64) {
        float mf = -1e30f, ms = -1e30f;
        for (int t = 0; t < 16; t++) {
            mf = fmaxf(mf, sm[tid * 32 + t]);
            ms = fmaxf(ms, sm[2048 + tid * 32 + t]);
        }
        g_Rf[blockIdx.y][g0 + tid] = mf;
        g_Rs[blockIdx.y][g0 + tid] = ms;
    }
}

// ---------------- kernel 1b: merge pool halves ----------------
__global__ void merge_kernel() {
    int i = blockIdx.x * 256 + threadIdx.x;
    g_RfM[i] = fmaxf(g_Rf[0][i], g_Rf[1][i]);
    g_RsM[i] = fmaxf(g_Rs[0][i], g_Rs[1][i]);
}

// ---------------- kernel 2: fused B x B pass ----------------
// grid (64 row-tiles, 2 col-splits of 2048). Per j-tile: pass1 gemms (f,s) ->
// mask bits in registers; pass2 gemms (z,zmix) -> fixed-shift LSE + weighted sums.
__global__ void __launch_bounds__(256, 1)
main_kernel(const float* __restrict__ z, const float* __restrict__ spr,
            const float* __restrict__ f, const float* __restrict__ zmix) {
    extern __shared__ float sm[];
    int tid = threadIdx.x, tx = tid >> 4, ty = tid & 15;
    int g0 = blockIdx.x * 64, col0 = blockIdx.y * 2048;
    float* AF  = sm;
    float* ASP = sm + 8448;
    float* AZ  = sm + 16896;
    float* AM  = sm + 25344;
    float* B0  = sm + 33792;
    float* B1  = sm + 42240;

    load_A_pairs(AF,  f,    g0, tid);
    load_A_pairs(ASP, spr,  g0, tid);
    load_A_pairs(AZ,  z,    g0, tid);
    load_A_pairs(AM,  zmix, g0, tid);

    float Rfr[4], Rsr[4];
#pragma unroll
    for (int r = 0; r < 4; r++) {
        int g = g0 + 4 * ty + r;
        Rfr[r] = g_RfM[g];
        Rsr[r] = g_RsM[g];
    }

    float Zz[4], Zm[4], Sz[4], Smm[4], ws[4], vc[4];
#pragma unroll
    for (int r = 0; r < 4; r++) {
        Zz[r] = 0.f; Zm[r] = 0.f; Sz[r] = 0.f; Smm[r] = 0.f; ws[r] = 0.f; vc[r] = 0.f;
    }

    for (int jt = 0; jt < 32; jt++) {
        int j0 = col0 + jt * 64;

        // ---- pass 1: masks ----
        __syncthreads();
        load_B_pairs(B0, f,   j0, tid);
        load_B_pairs(B1, spr, j0, tid);
        __syncthreads();

        float Rfc[4], Rsc[4];
#pragma unroll
        for (int c = 0; c < 4; c++) {
            int jj = j0 + tx * 4 + c;
            Rfc[c] = g_RfM[jj];
            Rsc[c] = g_RsM[jj];
        }
        unsigned nb[4];
        int wcol = (j0 + tx * 4) >> 5;
        int shift = (tx * 4) & 31;
#pragma unroll
        for (int r = 0; r < 4; r++) {
            int srow = (g0 + 4 * ty + r) & 255;
            nb[r] = (g_baseBits[srow * 128 + wcol] >> shift) & 15u;
        }

        unsigned long long cF[16], cS[16];
        gemm2(AF, ASP, B0, B1, ty, tx, cF, cS);

        unsigned bitsA = 0, bitsE = 0, bitsN = 0;
#pragma unroll
        for (int r = 0; r < 4; r++) {
            int i = g0 + 4 * ty + r;
#pragma unroll
            for (int c = 0; c < 4; c++) {
                int j = j0 + tx * 4 + c;
                float vf = red2(cF[r * 4 + c]);
                float vs = red2(cS[r * 4 + c]);
                bool neq = (j != i);
                bool m1 = (Rfr[r] < vf) | (Rfc[c] < vf);
                bool m2 = (Rsr[r] < vs) | (Rsc[c] < vs);
                bool nbc = ((nb[r] >> c) & 1u) != 0u;
                unsigned bit = 1u << (r * 4 + c);
                if (m1 & neq) bitsA |= bit;
                if (m2 & neq) bitsE |= bit;
                if ((m1 | nbc) & neq) bitsN |= bit;
            }
        }

        // ---- pass 2: logits ----
        __syncthreads();
        load_B_pairs(B0, z,    j0, tid);
        load_B_pairs(B1, zmix, j0, tid);
        __syncthreads();

        unsigned long long cZ[16], cM[16];
        gemm2(AZ, AM, B0, B1, ty, tx, cZ, cM);

#pragma unroll
        for (int r = 0; r < 4; r++) {
#pragma unroll
            for (int c = 0; c < 4; c++) {
                int idx = r * 4 + c;
                float vz = red2(cZ[idx]);
                float vm = red2(cM[idx]);
                float wA = ((bitsA >> idx) & 1u) ? 1.0f : 0.0f;
                float w  = wA + (((bitsE >> idx) & 1u) ? 0.5f : 0.0f);
                float en = ((bitsN >> idx) & 1u) ? 1.0f : 0.0f;
                Sz[r]  += w * vz;
                Smm[r] += w * vm;
                ws[r]  += w;
                vc[r]  += wA;
                Zz[r]  += en * ex2f(KE * (vz - 1.0f));
                Zm[r]  += en * ex2f(KE * (vm - 1.0f));
            }
        }
    }

    // ---- reduce across tx into per-row state ----
    __syncthreads();
#pragma unroll
    for (int r = 0; r < 4; r++) {
        int base = (4 * ty + r) * 96 + tx * 6;
        sm[base + 0] = Zz[r];
        sm[base + 1] = Zm[r];
        sm[base + 2] = Sz[r];
        sm[base + 3] = Smm[r];
        sm[base + 4] = ws[r];
        sm[base + 5] = vc[r];
    }
    __syncthreads();
    if (tid < 64) {
        float acc[6] = {0.f, 0.f, 0.f, 0.f, 0.f, 0.f};
        for (int t = 0; t < 16; t++)
#pragma unroll
            for (int q = 0; q < 6; q++) acc[q] += sm[tid * 96 + t * 6 + q];
#pragma unroll
        for (int q = 0; q < 6; q++)
            g_state[blockIdx.y][(size_t)(g0 + tid) * 6 + q] = acc[q];
    }
}

// ---------------- kernel 3: final scalar reduction ----------------
__global__ void reduce_kernel(float* __restrict__ out) {
    __shared__ float s1[256], s2[256];
    int tid = threadIdx.x;
    float grand = 0.f;
    for (int m = 0; m < 16; m++) {
        int i = m * 256 + tid;
        float q[6];
#pragma unroll
        for (int qn = 0; qn < 6; qn++)
            q[qn] = g_state[0][(size_t)i * 6 + qn] + g_state[1][(size_t)i * 6 + qn];
        float Zz = q[0], Zm = q[1], Sz = q[2], Sm = q[3], w = q[4], vcc = q[5];
        float num = 0.f, den = 0.f;
        if (vcc > 0.5f) {
            float lzz = INV_TEMP + LN2 * lg2f(Zz);
            float lzm = INV_TEMP + LN2 * lg2f(Zm);
            num = INV_TEMP * (Sz + Sm) - w * (lzz + lzm);
            den = w;
        }
        s1[tid] = num;
        s2[tid] = den;
        __syncthreads();
        for (int off = 128; off > 0; off >>= 1) {
            if (tid < off) { s1[tid] += s1[tid + off]; s2[tid] += s2[tid + off]; }
            __syncthreads();
        }
        if (tid == 0 && s2[0] != 0.f) grand += s1[0] / s2[0];
        __syncthreads();
    }
    if (tid == 0) out[0] = -grand / 32.0f;   // /M/2 with M=16
}

// ---------------- launch ----------------
extern "C" void kernel_launch(void* const* d_in, const int* in_sizes, int n_in,
                              void* d_out, int out_size) {
    const float* z    = (const float*)d_in[0];
    const float* spr  = (const float*)d_in[1];
    const float* f    = (const float*)d_in[2];
    const float* pag  = (const float*)d_in[3];
    const float* psp  = (const float*)d_in[4];
    const float* zmix = (const float*)d_in[5];
    const float* base = (const float*)d_in[6];
    float* out = (float*)d_out;

    const int SMEM_RMAX = 33792 * 4;   // 135168 B
    const int SMEM_MAIN = 50688 * 4;   // 202752 B
    cudaFuncSetAttribute(rmax_kernel, cudaFuncAttributeMaxDynamicSharedMemorySize, SMEM_RMAX);
    cudaFuncSetAttribute(main_kernel, cudaFuncAttributeMaxDynamicSharedMemorySize, SMEM_MAIN);

    pack_kernel<<<128, 256>>>(base);
    rmax_kernel<<<dim3(64, 2), 256, SMEM_RMAX>>>(f, spr, pag, psp);
    merge_kernel<<<16, 256>>>();
    main_kernel<<<dim3(64, 2), 256, SMEM_MAIN>>>(z, spr, f, zmix);
    reduce_kernel<<<1, 256>>>(out);
}

// round 4
// speedup vs baseline: 1.1114x; 1.1114x over previous
#include <cuda_runtime.h>
#include <math.h>

// ---------------- problem constants ----------------
#define NB 4096
#define ND 128
#define INV_TEMP 14.285714285714285714f          // 1/0.07
#define KE 20.609929155556619f                   // INV_TEMP * log2(e)
#define LN2 0.69314718055994531f

// ---------------- device scratch (no allocs) ----------------
__device__ float g_Rf[2][NB];
__device__ float g_Rs[2][NB];
__device__ float g_RfM[NB];
__device__ float g_RsM[NB];
__device__ unsigned g_baseBits[32768];           // [256 rows][128 words]
__device__ float g_state[2][NB * 6];             // {Zz, Zm, Sz, Sm, ws, vc}

// ---------------- small helpers ----------------
__device__ __forceinline__ unsigned long long ffma2(unsigned long long a,
                                                    unsigned long long b,
                                                    unsigned long long c) {
    unsigned long long d;
    asm("fma.rn.f32x2 %0, %1, %2, %3;" : "=l"(d) : "l"(a), "l"(b), "l"(c));
    return d;
}
__device__ __forceinline__ float red2(unsigned long long v) {
    float lo = __uint_as_float((unsigned)v);
    float hi = __uint_as_float((unsigned)(v >> 32));
    return lo + hi;
}
__device__ __forceinline__ float ex2f(float x) {
    float r; asm("ex2.approx.ftz.f32 %0, %1;" : "=f"(r) : "f"(x)); return r;
}
__device__ __forceinline__ float lg2f(float x) {
    float r; asm("lg2.approx.ftz.f32 %0, %1;" : "=f"(r) : "f"(x)); return r;
}

// ---------------- smem tile loaders ----------------
// A tile: 64 rows x 128 k -> 64 k-pair slices (pitch 132 floats = 528B).
// Within slice p, 16B chunk index (j*8 + ty) holds the k-pair for rows
// (ty*8 + 2j, ty*8 + 2j + 1). Read: thread ty issues 4 LDS.128 (j=0..3),
// warp addresses = 8 consecutive 16B chunks => conflict-free.
__device__ __forceinline__ void load_A(float* dst, const float* __restrict__ src,
                                       int g0, int tid) {
    for (int idx = tid; idx < 2048; idx += 256) {
        int row = idx >> 5, dv = idx & 31;
        float4 v = *(const float4*)(src + (size_t)(g0 + row) * ND + (dv << 2));
        int ty_ = row >> 3, rr = row & 7;
        int cbase = (((rr >> 1) << 3) + ty_) * 4 + (rr & 1) * 2;
        dst[(2 * dv) * 132 + cbase]         = v.x;   // k=4dv
        dst[(2 * dv) * 132 + cbase + 1]     = v.y;   // k=4dv+1
        dst[(2 * dv + 1) * 132 + cbase]     = v.z;   // k=4dv+2
        dst[(2 * dv + 1) * 132 + cbase + 1] = v.w;   // k=4dv+3
    }
}

// B tile: 64 cols x 128 k row-major, pitch 132 floats. Read as k-quads (LDS.128).
__device__ __forceinline__ void load_B(float* dst, const float* __restrict__ src,
                                       int j0, int tid) {
    for (int idx = tid; idx < 2048; idx += 256) {
        int n = idx >> 5, dv = idx & 31;
        *(float4*)(dst + n * 132 + (dv << 2)) =
            *(const float4*)(src + (size_t)(j0 + n) * ND + (dv << 2));
    }
}

// Single 64x64x128 gemm, 8x4 per-thread tile, f32x2 FMAs.
// acc[r*4+c] is the f32x2 (even/odd k) accumulator for row ty*8+r, col tx*4+c.
__device__ __forceinline__ void gemm84(const float* __restrict__ A,
                                       const float* __restrict__ B,
                                       int ty, int tx,
                                       unsigned long long acc[32]) {
#pragma unroll
    for (int i = 0; i < 32; i++) acc[i] = 0ull;
    const float* bp = B + tx * 4 * 132;
#pragma unroll 4
    for (int q = 0; q < 32; q++) {
        const float* s0 = A + (2 * q) * 132;
        const float* s1 = s0 + 132;
        unsigned long long aL[8], aH[8], bL[4], bH[4];
#pragma unroll
        for (int j = 0; j < 4; j++) {
            ulonglong2 c0 = *(const ulonglong2*)(s0 + ((j << 3) + ty) * 4);
            ulonglong2 c1 = *(const ulonglong2*)(s1 + ((j << 3) + ty) * 4);
            aL[2 * j] = c0.x; aL[2 * j + 1] = c0.y;
            aH[2 * j] = c1.x; aH[2 * j + 1] = c1.y;
        }
#pragma unroll
        for (int c = 0; c < 4; c++) {
            ulonglong2 cb = *(const ulonglong2*)(bp + c * 132 + 4 * q);
            bL[c] = cb.x; bH[c] = cb.y;
        }
#pragma unroll
        for (int r = 0; r < 8; r++)
#pragma unroll
            for (int c = 0; c < 4; c++) {
                acc[r * 4 + c] = ffma2(aL[r], bL[c], acc[r * 4 + c]);
                acc[r * 4 + c] = ffma2(aH[r], bH[c], acc[r * 4 + c]);
            }
    }
}

// ---------------- kernel 0: pack neglect-base mask to bits ----------------
__global__ void pack_kernel(const float* __restrict__ base) {
    int w = blockIdx.x * 256 + threadIdx.x;     // 32768 words
    const float* p = base + (size_t)w * 32;
    unsigned bits = 0;
#pragma unroll
    for (int b = 0; b < 32; b++) bits |= (p[b] > 0.f) ? (1u << b) : 0u;
    g_baseBits[w] = bits;
}

// ---------------- kernel 1: pool row-maxes ----------------
// grid (64 row-tiles, 2 pool-halves). group0: f x Pool_ag, group1: spr x Pool_sp.
__global__ void __launch_bounds__(256, 1)
rmax_kernel(const float* __restrict__ f, const float* __restrict__ spr,
            const float* __restrict__ pag, const float* __restrict__ psp) {
    extern __shared__ float sm[];
    int tid = threadIdx.x;
    int grp = tid >> 7, t = tid & 127, tx = t >> 3, ty = t & 7;
    int g0 = blockIdx.x * 64, p0 = blockIdx.y * 512;
    float* A0 = sm;
    float* A1 = sm + 8448;
    float* B0 = sm + 16896;
    float* B1 = sm + 25344;

    load_A(A0, f, g0, tid);
    load_A(A1, spr, g0, tid);

    const float* Am = grp ? A1 : A0;
    float rm[8];
#pragma unroll
    for (int r = 0; r < 8; r++) rm[r] = -1e30f;

    for (int jt = 0; jt < 8; jt++) {
        __syncthreads();
        load_B(B0, pag, p0 + jt * 64, tid);
        load_B(B1, psp, p0 + jt * 64, tid);
        __syncthreads();
        unsigned long long acc[32];
        gemm84(Am, grp ? B1 : B0, ty, tx, acc);
#pragma unroll
        for (int r = 0; r < 8; r++)
#pragma unroll
            for (int c = 0; c < 4; c++)
                rm[r] = fmaxf(rm[r], red2(acc[r * 4 + c]));
    }
    __syncthreads();
#pragma unroll
    for (int r = 0; r < 8; r++)
        sm[grp * 1024 + (ty * 8 + r) * 16 + tx] = rm[r];
    __syncthreads();
    if (tid < 64) {
        float mf = -1e30f, ms = -1e30f;
        for (int k = 0; k < 16; k++) {
            mf = fmaxf(mf, sm[tid * 16 + k]);
            ms = fmaxf(ms, sm[1024 + tid * 16 + k]);
        }
        g_Rf[blockIdx.y][g0 + tid] = mf;
        g_Rs[blockIdx.y][g0 + tid] = ms;
    }
}

// ---------------- kernel 1b: merge pool halves ----------------
__global__ void merge_kernel() {
    int i = blockIdx.x * 256 + threadIdx.x;
    g_RfM[i] = fmaxf(g_Rf[0][i], g_Rf[1][i]);
    g_RsM[i] = fmaxf(g_Rs[0][i], g_Rs[1][i]);
}

// ---------------- kernel 2: fused B x B pass ----------------
// grid (64 row-tiles, 2 col-splits). Per 64-col j-tile:
//   pass1: group0 gemm(f) -> bitsA/bitsN, group1 gemm(spr) -> bitsE; exchange.
//   pass2: group0 gemm(z) -> Zz/Sz (+counts), group1 gemm(zmix) -> Zm/Sm.
__global__ void __launch_bounds__(256, 1)
main_kernel(const float* __restrict__ z, const float* __restrict__ spr,
            const float* __restrict__ f, const float* __restrict__ zmix) {
    extern __shared__ float sm[];
    int tid = threadIdx.x;
    int grp = tid >> 7, t = tid & 127, tx = t >> 3, ty = t & 7;
    int g0 = blockIdx.x * 64, col0 = blockIdx.y * 2048;

    float* AF = sm;
    float* ASP = sm + 8448;
    float* AZ = sm + 16896;
    float* AM = sm + 25344;
    float* B0 = sm + 33792;
    float* B1 = sm + 42240;
    unsigned* maskA = (unsigned*)(sm + 50688);
    unsigned* maskN = maskA + 128;
    unsigned* maskE = maskA + 256;

    load_A(AF, f, g0, tid);
    load_A(ASP, spr, g0, tid);
    load_A(AZ, z, g0, tid);
    load_A(AM, zmix, g0, tid);

    const float* Rrow = grp ? g_RsM : g_RfM;
    float Rr[8];
#pragma unroll
    for (int r = 0; r < 8; r++) Rr[r] = Rrow[g0 + ty * 8 + r];

    // group0: st0=Zz, st1=Sz; group1: st0=Zm, st1=Sm
    float st0[8], st1[8];
    int cA[8], cE[8];
#pragma unroll
    for (int r = 0; r < 8; r++) { st0[r] = 0.f; st1[r] = 0.f; cA[r] = 0; cE[r] = 0; }

    for (int jt = 0; jt < 32; jt++) {
        int j0 = col0 + jt * 64;

        // ---- pass 1: masks ----
        __syncthreads();
        load_B(B0, f, j0, tid);
        load_B(B1, spr, j0, tid);
        __syncthreads();

        unsigned long long acc[32];
        gemm84(grp ? ASP : AF, grp ? B1 : B0, ty, tx, acc);

        float Rc[4];
#pragma unroll
        for (int c = 0; c < 4; c++) Rc[c] = Rrow[j0 + tx * 4 + c];

        if (grp == 0) {
            int wcol = (j0 + tx * 4) >> 5;
            int shift = (tx * 4) & 31;
            unsigned bA = 0, bN = 0;
#pragma unroll
            for (int r = 0; r < 8; r++) {
                int i = g0 + ty * 8 + r;
                unsigned nbw = (g_baseBits[(i & 255) * 128 + wcol] >> shift) & 15u;
#pragma unroll
                for (int c = 0; c < 4; c++) {
                    float v = red2(acc[r * 4 + c]);
                    bool m1 = (Rr[r] < v) | (Rc[c] < v);
                    bool neq = (i != (j0 + tx * 4 + c));
                    unsigned bit = 1u << (r * 4 + c);
                    if (m1 & neq) bA |= bit;
                    if ((m1 | (((nbw >> c) & 1u) != 0u)) & neq) bN |= bit;
                }
            }
            maskA[t] = bA;
            maskN[t] = bN;
        } else {
            unsigned bE = 0;
#pragma unroll
            for (int r = 0; r < 8; r++) {
                int i = g0 + ty * 8 + r;
#pragma unroll
                for (int c = 0; c < 4; c++) {
                    float v = red2(acc[r * 4 + c]);
                    bool m2 = (Rr[r] < v) | (Rc[c] < v);
                    bool neq = (i != (j0 + tx * 4 + c));
                    if (m2 & neq) bE |= 1u << (r * 4 + c);
                }
            }
            maskE[t] = bE;
        }

        // ---- pass 2: logits ----
        __syncthreads();
        load_B(B0, z, j0, tid);
        load_B(B1, zmix, j0, tid);
        __syncthreads();

        unsigned bA = maskA[t], bN = maskN[t], bE = maskE[t];
        gemm84(grp ? AM : AZ, grp ? B1 : B0, ty, tx, acc);

#pragma unroll
        for (int r = 0; r < 8; r++) {
            if (grp == 0) {
                cA[r] += __popc((bA >> (4 * r)) & 15u);
                cE[r] += __popc((bE >> (4 * r)) & 15u);
            }
#pragma unroll
            for (int c = 0; c < 4; c++) {
                int idx = r * 4 + c;
                float v = red2(acc[idx]);
                float w = (((bA >> idx) & 1u) ? 1.0f : 0.0f) +
                          (((bE >> idx) & 1u) ? 0.5f : 0.0f);
                st1[r] += w * v;
                float e = ex2f(KE * (v - 1.0f));
                if ((bN >> idx) & 1u) st0[r] += e;
            }
        }
    }

    // ---- block reduction across tx ----
    __syncthreads();
    if (grp == 0) {
#pragma unroll
        for (int r = 0; r < 8; r++) {
            int row = ty * 8 + r;
            sm[0 * 1024 + row * 16 + tx] = st0[r];          // Zz
            sm[1 * 1024 + row * 16 + tx] = st1[r];          // Sz
            sm[2 * 1024 + row * 16 + tx] = (float)cA[r];    // count A
            sm[3 * 1024 + row * 16 + tx] = (float)cE[r];    // count E
        }
    } else {
#pragma unroll
        for (int r = 0; r < 8; r++) {
            int row = ty * 8 + r;
            sm[4 * 1024 + row * 16 + tx] = st0[r];          // Zm
            sm[5 * 1024 + row * 16 + tx] = st1[r];          // Sm
        }
    }
    __syncthreads();
    if (tid < 64) {
        float a[6] = {0.f, 0.f, 0.f, 0.f, 0.f, 0.f};
        for (int k = 0; k < 16; k++)
#pragma unroll
            for (int q = 0; q < 6; q++) a[q] += sm[q * 1024 + tid * 16 + k];
        float* dst = &g_state[blockIdx.y][(size_t)(g0 + tid) * 6];
        dst[0] = a[0];                   // Zz
        dst[1] = a[4];                   // Zm
        dst[2] = a[1];                   // Sz
        dst[3] = a[5];                   // Sm
        dst[4] = a[2] + 0.5f * a[3];     // ws
        dst[5] = a[2];                   // vc
    }
}

// ---------------- kernel 3: final scalar reduction ----------------
__global__ void reduce_kernel(float* __restrict__ out) {
    __shared__ float s1[256], s2[256];
    int tid = threadIdx.x;
    float grand = 0.f;
    for (int m = 0; m < 16; m++) {
        int i = m * 256 + tid;
        float q[6];
#pragma unroll
        for (int qn = 0; qn < 6; qn++)
            q[qn] = g_state[0][(size_t)i * 6 + qn] + g_state[1][(size_t)i * 6 + qn];
        float Zz = q[0], Zm = q[1], Sz = q[2], Sm = q[3], w = q[4], vcc = q[5];
        float num = 0.f, den = 0.f;
        if (vcc > 0.5f) {
            float lzz = INV_TEMP + LN2 * lg2f(Zz);
            float lzm = INV_TEMP + LN2 * lg2f(Zm);
            num = INV_TEMP * (Sz + Sm) - w * (lzz + lzm);
            den = w;
        }
        s1[tid] = num;
        s2[tid] = den;
        __syncthreads();
        for (int off = 128; off > 0; off >>= 1) {
            if (tid < off) { s1[tid] += s1[tid + off]; s2[tid] += s2[tid + off]; }
            __syncthreads();
        }
        if (tid == 0 && s2[0] != 0.f) grand += s1[0] / s2[0];
        __syncthreads();
    }
    if (tid == 0) out[0] = -grand / 32.0f;   // /M/2 with M=16
}

// ---------------- launch ----------------
extern "C" void kernel_launch(void* const* d_in, const int* in_sizes, int n_in,
                              void* d_out, int out_size) {
    const float* z    = (const float*)d_in[0];
    const float* spr  = (const float*)d_in[1];
    const float* f    = (const float*)d_in[2];
    const float* pag  = (const float*)d_in[3];
    const float* psp  = (const float*)d_in[4];
    const float* zmix = (const float*)d_in[5];
    const float* base = (const float*)d_in[6];
    float* out = (float*)d_out;

    const int SMEM_RMAX = 33792 * 4;             // 135168 B
    const int SMEM_MAIN = 50688 * 4 + 1536;      // 204288 B
    cudaFuncSetAttribute(rmax_kernel, cudaFuncAttributeMaxDynamicSharedMemorySize, SMEM_RMAX);
    cudaFuncSetAttribute(main_kernel, cudaFuncAttributeMaxDynamicSharedMemorySize, SMEM_MAIN);

    pack_kernel<<<128, 256>>>(base);
    rmax_kernel<<<dim3(64, 2), 256, SMEM_RMAX>>>(f, spr, pag, psp);
    merge_kernel<<<16, 256>>>();
    main_kernel<<<dim3(64, 2), 256, SMEM_MAIN>>>(z, spr, f, zmix);
    reduce_kernel<<<1, 256>>>(out);
}